// round 1
// baseline (speedup 1.0000x reference)
#include <cuda_runtime.h>

// Sinkhorn as diagonal scaling: out = (s+eps) * u9[r] * v8[c] on the valid block.
// v_{2k} = 1/(M^T u_{2k-1}),  u_{2k+1} = 1/(M v_{2k}),  u_init = 1 on valid rows.
// Each streaming pass over s computes one (r, c) matvec pair.

#define NB   64
#define NN   1024
#define EPS  1e-4f

// Scratch (allocation-free rule: __device__ globals)
__device__ float g_acc[NB * NN];   // column-sum accumulator
__device__ float g_v[NB * NN];     // current column scales (0 on invalid cols)

__global__ void zero_acc_kernel() {
    int i = blockIdx.x * blockDim.x + threadIdx.x;
    if (i < NB * NN) g_acc[i] = 0.0f;
}

__global__ void finalize_v_kernel(const int* __restrict__ ncols) {
    int i = blockIdx.x * blockDim.x + threadIdx.x;
    if (i >= NB * NN) return;
    int b = i >> 10;
    int c = i & 1023;
    float a = g_acc[i];
    g_v[i]   = (c < ncols[b]) ? (1.0f / a) : 0.0f;
    g_acc[i] = 0.0f;   // ready for the next accumulating pass
}

// One streaming pass over s.
// FIRST=1: u=1 on valid rows (computes c0 only).
// FIRST=0: per valid row r: d = dot(row+eps, v); u = 1/d; acc[c] += (row[c]+eps)*u.
// Invalid columns are handled by v==0 there + finalize masking; column reads are
// trimmed to ceil(ncols/128)*128. Rows >= nrows are skipped entirely.
template <int FIRST>
__global__ __launch_bounds__(256, 2) void pass_kernel(
    const float* __restrict__ s,
    const int*   __restrict__ nrows,
    const int*   __restrict__ ncols)
{
    const int b  = blockIdx.y;
    const int nr = nrows[b];
    const int nc = ncols[b];
    const int r0cta = blockIdx.x * 64;
    if (r0cta >= nr) return;   // whole CTA invalid (uniform exit, before any sync)

    const int warp = threadIdx.x >> 5;
    const int lane = threadIdx.x & 31;
    const int fmax = min(8, (nc + 127) >> 7);

    const float4* sb = (const float4*)(s + (size_t)b * NN * NN);

    float4 v4[8];
#pragma unroll
    for (int f = 0; f < 8; f++) v4[f] = make_float4(0.f, 0.f, 0.f, 0.f);
    if (!FIRST) {
        const float4* vb = (const float4*)(g_v + b * NN);
#pragma unroll
        for (int f = 0; f < 8; f++)
            if (f < fmax) v4[f] = vb[f * 32 + lane];
    }

    float4 acc[8];
#pragma unroll
    for (int f = 0; f < 8; f++) acc[f] = make_float4(0.f, 0.f, 0.f, 0.f);

    const int rbase = r0cta + warp * 8;
    for (int i = 0; i < 8; i++) {
        int r = rbase + i;
        if (r >= nr) break;          // warp-uniform
        const float4* rp = sb + (size_t)r * 256;

        float4 x[8];
#pragma unroll
        for (int f = 0; f < 8; f++)
            if (f < fmax) x[f] = rp[f * 32 + lane];
#pragma unroll
        for (int f = 0; f < 8; f++)
            if (f < fmax) { x[f].x += EPS; x[f].y += EPS; x[f].z += EPS; x[f].w += EPS; }

        float u;
        if (FIRST) {
            u = 1.0f;
        } else {
            float d = 0.0f;
#pragma unroll
            for (int f = 0; f < 8; f++)
                if (f < fmax)
                    d += x[f].x * v4[f].x + x[f].y * v4[f].y
                       + x[f].z * v4[f].z + x[f].w * v4[f].w;
#pragma unroll
            for (int o = 16; o; o >>= 1) d += __shfl_xor_sync(0xffffffffu, d, o);
            u = 1.0f / d;
        }
#pragma unroll
        for (int f = 0; f < 8; f++)
            if (f < fmax) {
                acc[f].x += x[f].x * u; acc[f].y += x[f].y * u;
                acc[f].z += x[f].z * u; acc[f].w += x[f].w * u;
            }
    }

    // CTA-level reduction of per-warp column accumulators, then one REDG per column.
    __shared__ float4 st[8][256];
#pragma unroll
    for (int f = 0; f < 8; f++) st[warp][f * 32 + lane] = acc[f];
    __syncthreads();

    const int j = threadIdx.x;           // owns columns 4j..4j+3
    float4 t = st[0][j];
#pragma unroll
    for (int w = 1; w < 8; w++) {
        float4 a = st[w][j];
        t.x += a.x; t.y += a.y; t.z += a.z; t.w += a.w;
    }
    float* ga = g_acc + b * NN + 4 * j;
    atomicAdd(ga + 0, t.x);
    atomicAdd(ga + 1, t.y);
    atomicAdd(ga + 2, t.z);
    atomicAdd(ga + 3, t.w);
}

// Final pass: r9 = M v8 per row, u9 = 1/r9, write out = (s+eps)*u9*v8 (0 outside block).
__global__ __launch_bounds__(256, 2) void final_kernel(
    const float* __restrict__ s,
    float*       __restrict__ out,
    const int*   __restrict__ nrows,
    const int*   __restrict__ ncols)
{
    const int b  = blockIdx.y;
    const int nr = nrows[b];
    const int nc = ncols[b];
    const int warp = threadIdx.x >> 5;
    const int lane = threadIdx.x & 31;
    const int fmax = min(8, (nc + 127) >> 7);

    const float4* sb = (const float4*)(s + (size_t)b * NN * NN);
    float4*       ob = (float4*)(out + (size_t)b * NN * NN);
    const float4* vb = (const float4*)(g_v + b * NN);

    float4 v4[8];
#pragma unroll
    for (int f = 0; f < 8; f++)
        v4[f] = (f < fmax) ? vb[f * 32 + lane] : make_float4(0.f, 0.f, 0.f, 0.f);

    const int rbase = blockIdx.x * 64 + warp * 8;
    const float4 z4 = make_float4(0.f, 0.f, 0.f, 0.f);

    for (int i = 0; i < 8; i++) {
        int r = rbase + i;
        float4* op = ob + (size_t)r * 256;
        if (r >= nr) {                     // invalid row: all zeros (no read)
#pragma unroll
            for (int f = 0; f < 8; f++) op[f * 32 + lane] = z4;
            continue;
        }
        const float4* rp = sb + (size_t)r * 256;
        float4 x[8];
#pragma unroll
        for (int f = 0; f < 8; f++)
            if (f < fmax) x[f] = rp[f * 32 + lane];
#pragma unroll
        for (int f = 0; f < 8; f++)
            if (f < fmax) { x[f].x += EPS; x[f].y += EPS; x[f].z += EPS; x[f].w += EPS; }

        float d = 0.0f;
#pragma unroll
        for (int f = 0; f < 8; f++)
            if (f < fmax)
                d += x[f].x * v4[f].x + x[f].y * v4[f].y
                   + x[f].z * v4[f].z + x[f].w * v4[f].w;
#pragma unroll
        for (int o = 16; o; o >>= 1) d += __shfl_xor_sync(0xffffffffu, d, o);
        const float u = 1.0f / d;

#pragma unroll
        for (int f = 0; f < 8; f++) {
            if (f < fmax) {
                float4 o;
                o.x = x[f].x * u * v4[f].x;
                o.y = x[f].y * u * v4[f].y;
                o.z = x[f].z * u * v4[f].z;
                o.w = x[f].w * u * v4[f].w;
                op[f * 32 + lane] = o;     // v==0 beyond ncols -> exact 0
            } else {
                op[f * 32 + lane] = z4;
            }
        }
    }
}

extern "C" void kernel_launch(void* const* d_in, const int* in_sizes, int n_in,
                              void* d_out, int out_size)
{
    const float* s = (const float*)d_in[0];
    const int *nrows, *ncols;
    if (n_in >= 5) {          // order: s, n1, n2, nrows, ncols
        nrows = (const int*)d_in[3];
        ncols = (const int*)d_in[4];
    } else {                  // fallback: s, nrows, ncols
        nrows = (const int*)d_in[1];
        ncols = (const int*)d_in[2];
    }
    float* out = (float*)d_out;

    const dim3 grid(16, NB);   // 16 row-blocks of 64 rows x 64 batches
    const dim3 blk(256);
    const dim3 fgrid((NB * NN) / 256);

    zero_acc_kernel<<<fgrid, blk>>>();
    pass_kernel<1><<<grid, blk>>>(s, nrows, ncols);     // c0
    finalize_v_kernel<<<fgrid, blk>>>(ncols);           // v0
    for (int k = 0; k < 4; k++) {
        pass_kernel<0><<<grid, blk>>>(s, nrows, ncols); // (r1,c2)...(r7,c8)
        finalize_v_kernel<<<fgrid, blk>>>(ncols);       // v2, v4, v6, v8
    }
    final_kernel<<<grid, blk>>>(s, out, nrows, ncols);  // r9 -> u9 -> output
}

// round 2
// speedup vs baseline: 1.0451x; 1.0451x over previous
#include <cuda_runtime.h>

// Sinkhorn as diagonal scaling: out = (s+eps) * u9[r] * v8[c] on the valid block.
// v_{2k} = 1/(M^T u_{2k-1}),  u_{2k+1} = 1/(M v_{2k}),  u_init = 1 on valid rows.
// Each streaming pass over s computes one (row, col) matvec pair.
// R2: process batches in 2 groups of 32 so each group's working set (~82MB)
// stays L2-resident across its 6 passes; per-lane column trimming; finer CTAs;
// streaming output stores.

#define NB   64
#define NN   1024
#define EPS  1e-4f
#define GRP  32      // batches per group (L2 residency)
#define RPC  32      // rows per CTA

// Scratch (allocation-free rule: __device__ globals)
__device__ float g_acc[NB * NN];   // column-sum accumulator
__device__ float g_v[NB * NN];     // current column scales (0 on invalid cols)

__global__ void zero_acc_kernel() {
    int i = blockIdx.x * blockDim.x + threadIdx.x;
    if (i < NB * NN) g_acc[i] = 0.0f;
}

__global__ void finalize_v_kernel(const int* __restrict__ ncols, int batch0) {
    int i = blockIdx.x * blockDim.x + threadIdx.x;
    if (i >= GRP * NN) return;
    int b = batch0 + (i >> 10);
    int c = i & 1023;
    int gi = b * NN + c;
    float a = g_acc[gi];
    g_v[gi]   = (c < ncols[b]) ? (1.0f / a) : 0.0f;
    g_acc[gi] = 0.0f;   // ready for the next accumulating pass
}

// One streaming pass over one batch group.
// FIRST=1: u=1 on valid rows (computes c0 only).
// FIRST=0: per valid row r: d = dot(row+eps, v); u = 1/d; acc[c] += (row[c]+eps)*u.
// Loads trimmed per lane: float4 chunk f loaded iff 128*f < nc - 4*lane.
// Elements >= nc inside a loaded float4 are killed by v==0 + finalize masking.
template <int FIRST>
__global__ __launch_bounds__(256, 2) void pass_kernel(
    const float* __restrict__ s,
    const int*   __restrict__ nrows,
    const int*   __restrict__ ncols,
    int batch0)
{
    const int b  = batch0 + blockIdx.y;
    const int nr = nrows[b];
    const int r0cta = blockIdx.x * RPC;
    if (r0cta >= nr) return;   // whole CTA invalid (uniform exit, before any sync)

    const int nc   = ncols[b];
    const int warp = threadIdx.x >> 5;
    const int lane = threadIdx.x & 31;
    const int mylim = nc - 4 * lane;   // chunk f needed iff 128*f < mylim (>=388 always)

    const float4* sb = (const float4*)(s + (size_t)b * NN * NN);

    float4 v4[8];
#pragma unroll
    for (int f = 0; f < 8; f++) v4[f] = make_float4(0.f, 0.f, 0.f, 0.f);
    if (!FIRST) {
        const float4* vb = (const float4*)(g_v + b * NN);
#pragma unroll
        for (int f = 0; f < 8; f++)
            if (128 * f < mylim) v4[f] = vb[f * 32 + lane];
    }

    float4 acc[8];
#pragma unroll
    for (int f = 0; f < 8; f++) acc[f] = make_float4(0.f, 0.f, 0.f, 0.f);

    const int rbase = r0cta + warp * 4;
    for (int i = 0; i < 4; i++) {
        int r = rbase + i;
        if (r >= nr) break;          // warp-uniform
        const float4* rp = sb + (size_t)r * 256;

        float4 x[8];
#pragma unroll
        for (int f = 0; f < 8; f++)
            if (128 * f < mylim) x[f] = rp[f * 32 + lane];
#pragma unroll
        for (int f = 0; f < 8; f++)
            if (128 * f < mylim) { x[f].x += EPS; x[f].y += EPS; x[f].z += EPS; x[f].w += EPS; }

        float u;
        if (FIRST) {
            u = 1.0f;
        } else {
            float d = 0.0f;
#pragma unroll
            for (int f = 0; f < 8; f++)
                if (128 * f < mylim)
                    d += x[f].x * v4[f].x + x[f].y * v4[f].y
                       + x[f].z * v4[f].z + x[f].w * v4[f].w;
#pragma unroll
            for (int o = 16; o; o >>= 1) d += __shfl_xor_sync(0xffffffffu, d, o);
            u = 1.0f / d;
        }
#pragma unroll
        for (int f = 0; f < 8; f++)
            if (128 * f < mylim) {
                acc[f].x += x[f].x * u; acc[f].y += x[f].y * u;
                acc[f].z += x[f].z * u; acc[f].w += x[f].w * u;
            }
    }

    // CTA-level reduction of per-warp column accumulators, then one REDG per column.
    __shared__ float4 st[8][256];
#pragma unroll
    for (int f = 0; f < 8; f++) st[warp][f * 32 + lane] = acc[f];
    __syncthreads();

    const int j = threadIdx.x;           // owns columns 4j..4j+3
    float4 t = st[0][j];
#pragma unroll
    for (int w = 1; w < 8; w++) {
        float4 a = st[w][j];
        t.x += a.x; t.y += a.y; t.z += a.z; t.w += a.w;
    }
    float* ga = g_acc + b * NN + 4 * j;
    atomicAdd(ga + 0, t.x);
    atomicAdd(ga + 1, t.y);
    atomicAdd(ga + 2, t.z);
    atomicAdd(ga + 3, t.w);
}

// Final pass: r9 = M v8 per row, u9 = 1/r9, write out = (s+eps)*u9*v8 (0 outside block).
__global__ __launch_bounds__(256, 2) void final_kernel(
    const float* __restrict__ s,
    float*       __restrict__ out,
    const int*   __restrict__ nrows,
    const int*   __restrict__ ncols,
    int batch0)
{
    const int b  = batch0 + blockIdx.y;
    const int nr = nrows[b];
    const int nc = ncols[b];
    const int warp = threadIdx.x >> 5;
    const int lane = threadIdx.x & 31;
    const int mylim = nc - 4 * lane;

    const float4* sb = (const float4*)(s + (size_t)b * NN * NN);
    float4*       ob = (float4*)(out + (size_t)b * NN * NN);
    const float4* vb = (const float4*)(g_v + b * NN);

    float4 v4[8];
#pragma unroll
    for (int f = 0; f < 8; f++)
        v4[f] = (128 * f < mylim) ? vb[f * 32 + lane] : make_float4(0.f, 0.f, 0.f, 0.f);

    const int rbase = blockIdx.x * RPC + warp * 4;
    const float4 z4 = make_float4(0.f, 0.f, 0.f, 0.f);

    for (int i = 0; i < 4; i++) {
        int r = rbase + i;
        float4* op = ob + (size_t)r * 256;
        if (r >= nr) {                     // invalid row: all zeros (no read)
#pragma unroll
            for (int f = 0; f < 8; f++) __stcs(&op[f * 32 + lane], z4);
            continue;
        }
        const float4* rp = sb + (size_t)r * 256;
        float4 x[8];
#pragma unroll
        for (int f = 0; f < 8; f++)
            if (128 * f < mylim) x[f] = rp[f * 32 + lane];
#pragma unroll
        for (int f = 0; f < 8; f++)
            if (128 * f < mylim) { x[f].x += EPS; x[f].y += EPS; x[f].z += EPS; x[f].w += EPS; }

        float d = 0.0f;
#pragma unroll
        for (int f = 0; f < 8; f++)
            if (128 * f < mylim)
                d += x[f].x * v4[f].x + x[f].y * v4[f].y
                   + x[f].z * v4[f].z + x[f].w * v4[f].w;
#pragma unroll
        for (int o = 16; o; o >>= 1) d += __shfl_xor_sync(0xffffffffu, d, o);
        const float u = 1.0f / d;

#pragma unroll
        for (int f = 0; f < 8; f++) {
            if (128 * f < mylim) {
                float4 o;
                o.x = x[f].x * u * v4[f].x;
                o.y = x[f].y * u * v4[f].y;
                o.z = x[f].z * u * v4[f].z;
                o.w = x[f].w * u * v4[f].w;
                __stcs(&op[f * 32 + lane], o);   // v==0 beyond ncols -> exact 0
            } else {
                __stcs(&op[f * 32 + lane], z4);
            }
        }
    }
}

extern "C" void kernel_launch(void* const* d_in, const int* in_sizes, int n_in,
                              void* d_out, int out_size)
{
    const float* s = (const float*)d_in[0];
    const int *nrows, *ncols;
    if (n_in >= 5) {          // order: s, n1, n2, nrows, ncols
        nrows = (const int*)d_in[3];
        ncols = (const int*)d_in[4];
    } else {                  // fallback: s, nrows, ncols
        nrows = (const int*)d_in[1];
        ncols = (const int*)d_in[2];
    }
    float* out = (float*)d_out;

    const dim3 blk(256);
    const dim3 pgrid(NN / RPC, GRP);          // 32 row-CTAs x 32 batches
    const dim3 fgrid((GRP * NN) / 256);       // finalize over one group

    zero_acc_kernel<<<(NB * NN) / 256, blk>>>();

    for (int g = 0; g < NB / GRP; g++) {
        const int b0 = g * GRP;
        pass_kernel<1><<<pgrid, blk>>>(s, nrows, ncols, b0);      // c0
        finalize_v_kernel<<<fgrid, blk>>>(ncols, b0);             // v0
        for (int k = 0; k < 4; k++) {
            pass_kernel<0><<<pgrid, blk>>>(s, nrows, ncols, b0);  // (r1,c2)..(r7,c8)
            finalize_v_kernel<<<fgrid, blk>>>(ncols, b0);         // v2, v4, v6, v8
        }
        final_kernel<<<pgrid, blk>>>(s, out, nrows, ncols, b0);   // r9 -> u9 -> output
    }
}